// round 11
// baseline (speedup 1.0000x reference)
#include <cuda_runtime.h>

// CustomMeanIoU — fused kernel, phase-split (preds then targets) to halve
// concurrent DRAM streams, 16 px/thread for 8KB-per-class bursts, uniform
// one-tile-per-block work split. preds/targets: (16,19,512,512) fp32 NCHW.

#define NCLS 19
#define NIMG 16
#define HW (512 * 512)
#define EPSF 1e-6f

#define TPB 128
#define PXT 16                              // pixels per thread
#define TILE_PX (TPB * PXT)                 // 2048 px per block
#define TILES_PER_IMG (HW / TILE_PX)        // 128
#define GRID (TILES_PER_IMG * NIMG)         // 2048 blocks, uniform cost
#define STRIDE 132                          // u8 bytes per class row

__device__ unsigned int g_pred[NIMG * NCLS];
__device__ unsigned int g_targ[NIMG * NCLS];
__device__ unsigned int g_inter[NIMG * NCLS];
__device__ unsigned int g_count;

// Pack class index into low 5 mantissa bits: argmax == fmaxf chain (FMNMX).
__device__ __forceinline__ float pk(float v, int c) {
    return __int_as_float((__float_as_int(v) & ~31) | (31 - c));
}
__device__ __forceinline__ int unpk(float k) {
    return 31 - (__float_as_int(k) & 31);
}
__device__ __forceinline__ float4 ldcs4(const float* p) {
    return __ldcs((const float4*)p);
}

__global__ __launch_bounds__(TPB, 8) void miou_fused_kernel(
    const float* __restrict__ preds, const float* __restrict__ targs,
    const float* __restrict__ cw, float* __restrict__ out) {
    __shared__ unsigned char s_hist[3 * NCLS * STRIDE];  // 7524 B

    const int tid = threadIdx.x;
    const int x = blockIdx.x;        // tile within image
    const int n = blockIdx.y;        // image

    for (int i = tid; i < 3 * NCLS * STRIDE / 4; i += TPB)
        ((unsigned int*)s_hist)[i] = 0u;
    __syncthreads();

    unsigned char* s_pred = s_hist;
    unsigned char* s_targ = s_hist + NCLS * STRIDE;
    unsigned char* s_int  = s_hist + 2 * NCLS * STRIDE;

    // Thread's 4 float4 groups: tile_base + (tid + 128*i)*4 pixels.
    const size_t base_px = (size_t)n * NCLS * HW + (size_t)x * TILE_PX + (size_t)tid * 4;
    const float* p0 = preds + base_px;
    const float* t0 = targs + base_px;

    unsigned int a_pk[4];  // 16 pred labels, byte-packed

    // ---- Phase 1: preds ----
    {
        float k[PXT];
#pragma unroll
        for (int i = 0; i < 4; ++i) {
            float4 v = ldcs4(p0 + i * (TPB * 4));
            k[4 * i + 0] = pk(v.x, 0);
            k[4 * i + 1] = pk(v.y, 0);
            k[4 * i + 2] = pk(v.z, 0);
            k[4 * i + 3] = pk(v.w, 0);
        }
#pragma unroll
        for (int c = 1; c < NCLS; ++c) {
#pragma unroll
            for (int i = 0; i < 4; ++i) {
                float4 v = ldcs4(p0 + (size_t)c * HW + i * (TPB * 4));
                k[4 * i + 0] = fmaxf(k[4 * i + 0], pk(v.x, c));
                k[4 * i + 1] = fmaxf(k[4 * i + 1], pk(v.y, c));
                k[4 * i + 2] = fmaxf(k[4 * i + 2], pk(v.z, c));
                k[4 * i + 3] = fmaxf(k[4 * i + 3], pk(v.w, c));
            }
        }
#pragma unroll
        for (int q = 0; q < 4; ++q) {
            unsigned int w = 0;
#pragma unroll
            for (int j = 0; j < 4; ++j) {
                const int a = unpk(k[4 * q + j]);
                w |= (unsigned int)a << (8 * j);
                s_pred[a * STRIDE + tid]++;
            }
            a_pk[q] = w;
        }
    }

    // ---- Phase 2: targets ----
    {
        float k[PXT];
#pragma unroll
        for (int i = 0; i < 4; ++i) {
            float4 v = ldcs4(t0 + i * (TPB * 4));
            k[4 * i + 0] = pk(v.x, 0);
            k[4 * i + 1] = pk(v.y, 0);
            k[4 * i + 2] = pk(v.z, 0);
            k[4 * i + 3] = pk(v.w, 0);
        }
#pragma unroll
        for (int c = 1; c < NCLS; ++c) {
#pragma unroll
            for (int i = 0; i < 4; ++i) {
                float4 v = ldcs4(t0 + (size_t)c * HW + i * (TPB * 4));
                k[4 * i + 0] = fmaxf(k[4 * i + 0], pk(v.x, c));
                k[4 * i + 1] = fmaxf(k[4 * i + 1], pk(v.y, c));
                k[4 * i + 2] = fmaxf(k[4 * i + 2], pk(v.z, c));
                k[4 * i + 3] = fmaxf(k[4 * i + 3], pk(v.w, c));
            }
        }
#pragma unroll
        for (int q = 0; q < 4; ++q) {
#pragma unroll
            for (int j = 0; j < 4; ++j) {
                const int b = unpk(k[4 * q + j]);
                const int a = (int)((a_pk[q] >> (8 * j)) & 31u);
                s_targ[b * STRIDE + tid]++;
                if (a == b) s_int[a * STRIDE + tid]++;
            }
        }
    }

    __syncthreads();

    // Reduce 57 u8 counter rows (128 bytes each) with dp4a byte-sums.
    const int wid = tid >> 5;
    const int lane = tid & 31;
    for (int k = wid; k < 3 * NCLS; k += TPB / 32) {
        const unsigned int* row = (const unsigned int*)(s_hist + k * STRIDE);
        unsigned int v = __dp4a(row[lane], 0x01010101u, 0u);
#pragma unroll
        for (int s = 16; s > 0; s >>= 1) v += __shfl_down_sync(0xffffffffu, v, s);
        if (lane == 0 && v != 0u) {
            const int kind = k / NCLS;
            const int c = k % NCLS;
            unsigned int* dst = (kind == 0) ? g_pred : (kind == 1) ? g_targ : g_inter;
            atomicAdd(&dst[n * NCLS + c], v);
        }
    }

    // ---- last-block-done finalize ----
    __shared__ unsigned int s_done;
    __threadfence();
    __syncthreads();
    if (tid == 0) s_done = atomicAdd(&g_count, 1u);
    __syncthreads();
    if (s_done != GRID - 1) return;

    __shared__ float s_red[4];
    float acc = 0.0f;
    for (int i = tid; i < NIMG * NCLS; i += TPB) {
        const int c = i % NCLS;
        const float inter = (float)((volatile unsigned int*)g_inter)[i];
        const float pc = (float)((volatile unsigned int*)g_pred)[i];
        const float tc = (float)((volatile unsigned int*)g_targ)[i];
        const float uni = pc + tc - inter;
        acc += cw[c] * (inter + EPSF) / (uni + EPSF);
    }
#pragma unroll
    for (int s = 16; s > 0; s >>= 1) acc += __shfl_down_sync(0xffffffffu, acc, s);
    if (lane == 0) s_red[wid] = acc;
    __syncthreads();
    if (tid == 0) {
        out[0] = (s_red[0] + s_red[1] + s_red[2] + s_red[3]) / (float)(NIMG * NCLS);
    }

    // Reset accumulators for next graph replay.
    __syncthreads();
    for (int i = tid; i < NIMG * NCLS; i += TPB) {
        g_pred[i] = 0u;
        g_targ[i] = 0u;
        g_inter[i] = 0u;
    }
    if (tid == 0) g_count = 0u;
}

extern "C" void kernel_launch(void* const* d_in, const int* in_sizes, int n_in,
                              void* d_out, int out_size) {
    const float* preds = (const float*)d_in[0];
    const float* targs = (const float*)d_in[1];
    const float* cw = (const float*)d_in[2];
    float* out = (float*)d_out;

    dim3 grid(TILES_PER_IMG, NIMG);
    miou_fused_kernel<<<grid, TPB>>>(preds, targs, cw, out);
}

// round 12
// speedup vs baseline: 1.0895x; 1.0895x over previous
#include <cuda_runtime.h>

// CustomMeanIoU — fused kernel, packed-key argmax, u8 per-thread histograms.
// Champion config (R4: 4px/thread, 74x16 grid, 8 blocks/SM) + __ldcs streaming.
// preds/targets: (16, 19, 512, 512) fp32 NCHW. 637MB reads -> HBM floor ~80us.

#define NCLS 19
#define NIMG 16
#define HW (512 * 512)
#define EPSF 1e-6f

#define TPB 128
#define BLOCKS_X 74                       // per image
#define GRID (BLOCKS_X * NIMG)            // 1184 = 148 SMs * 8 blocks
#define GROUPS_PER_IMG (HW / 4)           // 65536 float4 groups
#define STRIDE 132                        // u8 bytes per class row (bank spread)

__device__ unsigned int g_pred[NIMG * NCLS];
__device__ unsigned int g_targ[NIMG * NCLS];
__device__ unsigned int g_inter[NIMG * NCLS];
__device__ unsigned int g_count;

// Pack class index into low 5 mantissa bits so argmax = fmaxf chain (FMNMX).
__device__ __forceinline__ float pk(float v, int c) {
    return __int_as_float((__float_as_int(v) & ~31) | (31 - c));
}
__device__ __forceinline__ int unpk(float k) {
    return 31 - (__float_as_int(k) & 31);
}
__device__ __forceinline__ float4 ldcs4(const float* p) {
    return __ldcs((const float4*)p);
}

__global__ __launch_bounds__(TPB, 8) void miou_fused_kernel(
    const float* __restrict__ preds, const float* __restrict__ targs,
    const float* __restrict__ cw, float* __restrict__ out) {
    __shared__ unsigned char s_hist[3 * NCLS * STRIDE];  // 7524 B

    const int tid = threadIdx.x;
    const int n = blockIdx.y;

    for (int i = tid; i < 3 * NCLS * STRIDE / 4; i += TPB)
        ((unsigned int*)s_hist)[i] = 0u;
    __syncthreads();

    unsigned char* s_pred = s_hist;
    unsigned char* s_targ = s_hist + NCLS * STRIDE;
    unsigned char* s_int  = s_hist + 2 * NCLS * STRIDE;

    const float* pbase = preds + (size_t)n * NCLS * HW;
    const float* tbase = targs + (size_t)n * NCLS * HW;

    for (int g = blockIdx.x * TPB + tid; g < GROUPS_PER_IMG; g += BLOCKS_X * TPB) {
        const int off = g * 4;

        float4 p = ldcs4(pbase + off);
        float4 t = ldcs4(tbase + off);
        float k0 = pk(p.x, 0), k1 = pk(p.y, 0), k2 = pk(p.z, 0), k3 = pk(p.w, 0);
        float j0 = pk(t.x, 0), j1 = pk(t.y, 0), j2 = pk(t.z, 0), j3 = pk(t.w, 0);

#pragma unroll
        for (int c = 1; c < NCLS; ++c) {
            const int co = c * HW + off;
            float4 pc = ldcs4(pbase + co);
            float4 tc = ldcs4(tbase + co);
            k0 = fmaxf(k0, pk(pc.x, c));
            k1 = fmaxf(k1, pk(pc.y, c));
            k2 = fmaxf(k2, pk(pc.z, c));
            k3 = fmaxf(k3, pk(pc.w, c));
            j0 = fmaxf(j0, pk(tc.x, c));
            j1 = fmaxf(j1, pk(tc.y, c));
            j2 = fmaxf(j2, pk(tc.z, c));
            j3 = fmaxf(j3, pk(tc.w, c));
        }

        const int a0 = unpk(k0), a1 = unpk(k1), a2 = unpk(k2), a3 = unpk(k3);
        const int b0 = unpk(j0), b1 = unpk(j1), b2 = unpk(j2), b3 = unpk(j3);

        s_pred[a0 * STRIDE + tid]++;
        s_pred[a1 * STRIDE + tid]++;
        s_pred[a2 * STRIDE + tid]++;
        s_pred[a3 * STRIDE + tid]++;
        s_targ[b0 * STRIDE + tid]++;
        s_targ[b1 * STRIDE + tid]++;
        s_targ[b2 * STRIDE + tid]++;
        s_targ[b3 * STRIDE + tid]++;
        if (a0 == b0) s_int[a0 * STRIDE + tid]++;
        if (a1 == b1) s_int[a1 * STRIDE + tid]++;
        if (a2 == b2) s_int[a2 * STRIDE + tid]++;
        if (a3 == b3) s_int[a3 * STRIDE + tid]++;
    }

    __syncthreads();

    // Reduce 57 u8 counter rows (128 bytes each) with dp4a byte-sums.
    const int wid = tid >> 5;
    const int lane = tid & 31;
    for (int k = wid; k < 3 * NCLS; k += TPB / 32) {
        const unsigned int* row = (const unsigned int*)(s_hist + k * STRIDE);
        unsigned int v = __dp4a(row[lane], 0x01010101u, 0u);
#pragma unroll
        for (int s = 16; s > 0; s >>= 1) v += __shfl_down_sync(0xffffffffu, v, s);
        if (lane == 0 && v != 0u) {
            const int kind = k / NCLS;
            const int c = k % NCLS;
            unsigned int* dst = (kind == 0) ? g_pred : (kind == 1) ? g_targ : g_inter;
            atomicAdd(&dst[n * NCLS + c], v);
        }
    }

    // ---- last-block-done finalize ----
    __shared__ unsigned int s_done;
    __threadfence();
    __syncthreads();
    if (tid == 0) s_done = atomicAdd(&g_count, 1u);
    __syncthreads();
    if (s_done != GRID - 1) return;

    __shared__ float s_red[4];
    float acc = 0.0f;
    for (int i = tid; i < NIMG * NCLS; i += TPB) {
        const int c = i % NCLS;
        const float inter = (float)((volatile unsigned int*)g_inter)[i];
        const float pc = (float)((volatile unsigned int*)g_pred)[i];
        const float tc = (float)((volatile unsigned int*)g_targ)[i];
        const float uni = pc + tc - inter;
        acc += cw[c] * (inter + EPSF) / (uni + EPSF);
    }
#pragma unroll
    for (int s = 16; s > 0; s >>= 1) acc += __shfl_down_sync(0xffffffffu, acc, s);
    if (lane == 0) s_red[wid] = acc;
    __syncthreads();
    if (tid == 0) {
        out[0] = (s_red[0] + s_red[1] + s_red[2] + s_red[3]) / (float)(NIMG * NCLS);
    }

    // Reset accumulators for next graph replay.
    __syncthreads();
    for (int i = tid; i < NIMG * NCLS; i += TPB) {
        g_pred[i] = 0u;
        g_targ[i] = 0u;
        g_inter[i] = 0u;
    }
    if (tid == 0) g_count = 0u;
}

extern "C" void kernel_launch(void* const* d_in, const int* in_sizes, int n_in,
                              void* d_out, int out_size) {
    const float* preds = (const float*)d_in[0];
    const float* targs = (const float*)d_in[1];
    const float* cw = (const float*)d_in[2];
    float* out = (float*)d_out;

    dim3 grid(BLOCKS_X, NIMG);
    miou_fused_kernel<<<grid, TPB>>>(preds, targs, cw, out);
}